// round 3
// baseline (speedup 1.0000x reference)
#include <cuda_runtime.h>
#include <math.h>

#define BATCH 8192
#define FULL 0xffffffffu

// Scratch (no allocation allowed -> device globals)
__device__ float g_h1[BATCH * 32];
__device__ float g_h2[BATCH * 16];
__device__ float g_Wt[256 * 64];   // fW1 transposed: [k][o]
__device__ float g_U[6 * 8 * 8];   // [layer][qubit][u00r,u00i,u01r,u01i,u10r,u10i,u11r,u11i]
__device__ float g_stat1[64];      // mean[32], rstd[32]
__device__ float g_stat2[32];      // mean[16], rstd[16]

// ---------------------------------------------------------------------------
// Prep: fused rotation matrices U = RZ*RY*RX per (layer,qubit); transpose fW1.
// ---------------------------------------------------------------------------
__global__ void prep_kernel(const float* __restrict__ qw, const float* __restrict__ fW1) {
    int t = threadIdx.x;
    if (t < 48) {
        int l = t / 8, q = t % 8;
        float ax = qw[l * 24 + 3 * q + 0] * 0.5f;
        float ay = qw[l * 24 + 3 * q + 1] * 0.5f;
        float az = qw[l * 24 + 3 * q + 2] * 0.5f;
        float cx, sx, cy, sy, cz, sz;
        sincosf(ax, &sx, &cx);
        sincosf(ay, &sy, &cy);
        sincosf(az, &sz, &cz);
        // M = RY*RX:
        // m00 = cy cx + i sy sx ; m01 = -sy cx - i cy sx
        // m10 = sy cx - i cy sx ; m11 =  cy cx - i sy sx
        float m00r = cy * cx, m00i = sy * sx;
        float m01r = -sy * cx, m01i = -cy * sx;
        float m10r = sy * cx, m10i = -cy * sx;
        float m11r = cy * cx, m11i = -sy * sx;
        float* u = &g_U[t * 8];
        // row0 *= (cz - i sz); row1 *= (cz + i sz)
        u[0] = cz * m00r + sz * m00i;  u[1] = cz * m00i - sz * m00r;
        u[2] = cz * m01r + sz * m01i;  u[3] = cz * m01i - sz * m01r;
        u[4] = cz * m10r - sz * m10i;  u[5] = cz * m10i + sz * m10r;
        u[6] = cz * m11r - sz * m11i;  u[7] = cz * m11i + sz * m11r;
    }
    for (int idx = t; idx < 64 * 256; idx += blockDim.x) {
        int o = idx >> 8, k = idx & 255;
        g_Wt[k * 64 + o] = fW1[idx];
    }
}

// ---------------------------------------------------------------------------
// CNOT helpers (state: sr[8]/si[8] per lane; lane = amp bits 7..3)
// ---------------------------------------------------------------------------
#define CNOT_LL(cm, tm)                                                        \
    {                                                                          \
        _Pragma("unroll") for (int j = 0; j < 8; j++) {                        \
            float orr = __shfl_xor_sync(FULL, sr[j], (tm));                    \
            float ori = __shfl_xor_sync(FULL, si[j], (tm));                    \
            if (lane & (cm)) { sr[j] = orr; si[j] = ori; }                     \
        }                                                                      \
    }

#define CNOT_LT(cm, mb)                                                        \
    {                                                                          \
        bool f = (lane & (cm)) != 0;                                           \
        _Pragma("unroll") for (int j = 0; j < 8; j++) {                        \
            if (j & (mb)) continue;                                            \
            int j1 = j | (mb);                                                 \
            float t0r = sr[j], t0i = si[j];                                    \
            sr[j] = f ? sr[j1] : sr[j];                                        \
            si[j] = f ? si[j1] : si[j];                                        \
            sr[j1] = f ? t0r : sr[j1];                                         \
            si[j1] = f ? t0i : si[j1];                                         \
        }                                                                      \
    }

#define CNOT_TL(mb, tm)                                                        \
    {                                                                          \
        _Pragma("unroll") for (int j = 0; j < 8; j++) {                        \
            if (!(j & (mb))) continue;                                         \
            sr[j] = __shfl_xor_sync(FULL, sr[j], (tm));                        \
            si[j] = __shfl_xor_sync(FULL, si[j], (tm));                        \
        }                                                                      \
    }

#define CNOT_TT(cmb, tmb)                                                      \
    {                                                                          \
        _Pragma("unroll") for (int j = 0; j < 8; j++) {                        \
            if (!((j & (cmb)) && !(j & (tmb)))) continue;                      \
            int j1 = j | (tmb);                                                \
            float tr = sr[j]; sr[j] = sr[j1]; sr[j1] = tr;                     \
            float ti = si[j]; si[j] = si[j1]; si[j1] = ti;                     \
        }                                                                      \
    }

// ---------------------------------------------------------------------------
// K1: quantum circuit + adapter + feature_processor + cW1 -> g_h1 (pre-BN)
// One warp per batch row. 8 rows per 256-thread block.
// ---------------------------------------------------------------------------
__global__ void __launch_bounds__(256) qnn_kernel(
    const float* __restrict__ x,
    const float* __restrict__ aW, const float* __restrict__ ab,
    const float* __restrict__ fb1,
    const float* __restrict__ fW2, const float* __restrict__ fb2,
    const float* __restrict__ cW1, const float* __restrict__ cb1)
{
    __shared__ float xs[8][256];
    int lane = threadIdx.x & 31;
    int wid = threadIdx.x >> 5;
    int row = blockIdx.x * 8 + wid;

    const float4* xp = (const float4*)(x + row * 256);
    float4 xa = xp[lane * 2];
    float4 xb = xp[lane * 2 + 1];
    ((float4*)xs[wid])[lane * 2] = xa;
    ((float4*)xs[wid])[lane * 2 + 1] = xb;
    __syncwarp();

    float xl[8] = {xa.x, xa.y, xa.z, xa.w, xb.x, xb.y, xb.z, xb.w};
    float nsq = 0.f;
#pragma unroll
    for (int j = 0; j < 8; j++) nsq += xl[j] * xl[j];
#pragma unroll
    for (int o = 16; o; o >>= 1) nsq += __shfl_xor_sync(FULL, nsq, o);
    float inv = rsqrtf(nsq);

    float sr[8], si[8];
#pragma unroll
    for (int j = 0; j < 8; j++) { sr[j] = xl[j] * inv; si[j] = 0.f; }

#pragma unroll 1
    for (int l = 0; l < 6; l++) {
        const float* Ul = &g_U[l * 64];
        // wires 0..4 : lane-bit gates (masks 16..1)
        for (int q = 0; q < 5; q++) {
            const float* u = &Ul[q * 8];
            int m = 16 >> q;
            bool hi = (lane & m) != 0;
            float csr = hi ? u[6] : u[0], csi = hi ? u[7] : u[1];
            float cor = hi ? u[4] : u[2], coi = hi ? u[5] : u[3];
#pragma unroll
            for (int j = 0; j < 8; j++) {
                float orr = __shfl_xor_sync(FULL, sr[j], m);
                float ori = __shfl_xor_sync(FULL, si[j], m);
                float nr = csr * sr[j] - csi * si[j] + cor * orr - coi * ori;
                float ni = csr * si[j] + csi * sr[j] + cor * ori + coi * orr;
                sr[j] = nr; si[j] = ni;
            }
        }
        // wires 5,6,7 : local-bit gates (bits 2,1,0)
#pragma unroll
        for (int q = 5; q < 8; q++) {
            const float* u = &Ul[q * 8];
            int mb = 1 << (7 - q);
#pragma unroll
            for (int j = 0; j < 8; j++) {
                if (j & mb) continue;
                int j1 = j | mb;
                float ar = sr[j], ai = si[j], br = sr[j1], bi = si[j1];
                sr[j]  = u[0] * ar - u[1] * ai + u[2] * br - u[3] * bi;
                si[j]  = u[0] * ai + u[1] * ar + u[2] * bi + u[3] * br;
                sr[j1] = u[4] * ar - u[5] * ai + u[6] * br - u[7] * bi;
                si[j1] = u[4] * ai + u[5] * ar + u[6] * bi + u[7] * br;
            }
        }
        // CNOT ring + extras. wire w -> amp bit (7-w); lane bit k = amp bit 3+k.
        CNOT_LL(16, 8);   // (0,1)
        CNOT_LL(8, 4);    // (1,2)
        CNOT_LL(4, 2);    // (2,3)
        CNOT_LL(2, 1);    // (3,4)
        CNOT_LT(1, 4);    // (4,5): ctrl lane bit0, tgt local bit2
        CNOT_TT(4, 2);    // (5,6)
        CNOT_TT(2, 1);    // (6,7)
        CNOT_TL(1, 16);   // (7,0): ctrl local bit0, tgt lane bit4
        CNOT_LL(16, 4);   // (0,2)
        CNOT_LL(4, 1);    // (2,4)
        CNOT_LT(1, 2);    // (4,6)
    }

    // Z expectations on wires 0..3 (lane bits 4..1)
    float p = 0.f;
#pragma unroll
    for (int j = 0; j < 8; j++) p += sr[j] * sr[j] + si[j] * si[j];
    float z[4];
#pragma unroll
    for (int w = 0; w < 4; w++) {
        int m = 16 >> w;
        float v = (lane & m) ? -p : p;
#pragma unroll
        for (int o = 16; o; o >>= 1) v += __shfl_xor_sync(FULL, v, o);
        z[w] = v;
    }
    float qf[4];
#pragma unroll
    for (int i = 0; i < 4; i++)
        qf[i] = ab[i] + aW[i * 4 + 0] * z[0] + aW[i * 4 + 1] * z[1]
                      + aW[i * 4 + 2] * z[2] + aW[i * 4 + 3] * z[3];

    // feature_processor: lane owns outputs 2*lane, 2*lane+1
    float acc0 = fb1[lane * 2], acc1 = fb1[lane * 2 + 1];
    const float2* W2p = (const float2*)g_Wt;
    const float* xw = xs[wid];
#pragma unroll 4
    for (int k = 0; k < 256; k++) {
        float xk = xw[k];
        float2 wv = W2p[k * 32 + lane];
        acc0 = fmaf(xk, wv.x, acc0);
        acc1 = fmaf(xk, wv.y, acc1);
    }
    acc0 = fmaxf(acc0, 0.f);
    acc1 = fmaxf(acc1, 0.f);
    float cf[4];
#pragma unroll
    for (int i = 0; i < 4; i++) {
        float2 w2 = ((const float2*)fW2)[i * 32 + lane];
        float v = acc0 * w2.x + acc1 * w2.y;
#pragma unroll
        for (int o = 16; o; o >>= 1) v += __shfl_xor_sync(FULL, v, o);
        cf[i] = tanhf(v + fb2[i]);
    }

    float hh[4];
#pragma unroll
    for (int i = 0; i < 4; i++) hh[i] = qf[i] + cf[i];

    float4 w1 = ((const float4*)cW1)[lane];
    float h1v = cb1[lane] + w1.x * hh[0] + w1.y * hh[1] + w1.z * hh[2] + w1.w * hh[3];
    g_h1[row * 32 + lane] = h1v;
}

// ---------------------------------------------------------------------------
// Deterministic batch stats (single block, fixed-order tree)
// ---------------------------------------------------------------------------
__global__ void stats1_kernel() {
    __shared__ double sbuf[1024];
    __shared__ double s2buf[1024];
    int t = threadIdx.x;
    double s = 0.0, s2 = 0.0;
    for (int i = 0; i < (BATCH * 32) / 1024; i++) {
        float v = g_h1[t + 1024 * i];
        s += v;
        s2 += (double)v * v;
    }
    sbuf[t] = s;
    s2buf[t] = s2;
    __syncthreads();
    if (t < 32) {
        double ts = 0.0, ts2 = 0.0;
        for (int k = 0; k < 32; k++) { ts += sbuf[t + 32 * k]; ts2 += s2buf[t + 32 * k]; }
        double mean = ts / BATCH;
        double var = ts2 / BATCH - mean * mean;
        g_stat1[t] = (float)mean;
        g_stat1[32 + t] = rsqrtf((float)var + 1e-5f);
    }
}

__global__ void stats2_kernel() {
    __shared__ double sbuf[1024];
    __shared__ double s2buf[1024];
    int t = threadIdx.x;
    double s = 0.0, s2 = 0.0;
    for (int i = 0; i < (BATCH * 16) / 1024; i++) {
        float v = g_h2[t + 1024 * i];
        s += v;
        s2 += (double)v * v;
    }
    sbuf[t] = s;
    s2buf[t] = s2;
    __syncthreads();
    if (t < 16) {
        double ts = 0.0, ts2 = 0.0;
        for (int k = 0; k < 64; k++) { ts += sbuf[t + 16 * k]; ts2 += s2buf[t + 16 * k]; }
        double mean = ts / BATCH;
        double var = ts2 / BATCH - mean * mean;
        g_stat2[t] = (float)mean;
        g_stat2[16 + t] = rsqrtf((float)var + 1e-5f);
    }
}

// ---------------------------------------------------------------------------
// K3: BN1 + relu + cW2 -> g_h2 (pre-BN2). One thread per row.
// ---------------------------------------------------------------------------
__global__ void __launch_bounds__(256) bn1_kernel(
    const float* __restrict__ g1, const float* __restrict__ be1,
    const float* __restrict__ cW2, const float* __restrict__ cb2)
{
    int r = blockIdx.x * blockDim.x + threadIdx.x;
    float a[32];
    const float4* hp = (const float4*)&g_h1[r * 32];
#pragma unroll
    for (int j4 = 0; j4 < 8; j4++) {
        float4 v = hp[j4];
        float vv[4] = {v.x, v.y, v.z, v.w};
#pragma unroll
        for (int c = 0; c < 4; c++) {
            int j = j4 * 4 + c;
            float m = g_stat1[j], rs = g_stat1[32 + j];
            a[j] = fmaxf(g1[j] * (vv[c] - m) * rs + be1[j], 0.f);
        }
    }
    float o4[4];
#pragma unroll
    for (int i4 = 0; i4 < 4; i4++) {
#pragma unroll
        for (int c = 0; c < 4; c++) {
            int i = i4 * 4 + c;
            float acc = cb2[i];
#pragma unroll
            for (int j = 0; j < 32; j++) acc = fmaf(cW2[i * 32 + j], a[j], acc);
            o4[c] = acc;
        }
        ((float4*)&g_h2[r * 16])[i4] = make_float4(o4[0], o4[1], o4[2], o4[3]);
    }
}

// ---------------------------------------------------------------------------
// K5: BN2 + relu + cW3 + relu + cW4 + sigmoid -> out. One thread per row.
// ---------------------------------------------------------------------------
__global__ void __launch_bounds__(256) final_kernel(
    const float* __restrict__ g2, const float* __restrict__ be2,
    const float* __restrict__ cW3, const float* __restrict__ cb3,
    const float* __restrict__ cW4, const float* __restrict__ cb4,
    float* __restrict__ out)
{
    int r = blockIdx.x * blockDim.x + threadIdx.x;
    float a[16];
    const float4* hp = (const float4*)&g_h2[r * 16];
#pragma unroll
    for (int j4 = 0; j4 < 4; j4++) {
        float4 v = hp[j4];
        float vv[4] = {v.x, v.y, v.z, v.w};
#pragma unroll
        for (int c = 0; c < 4; c++) {
            int j = j4 * 4 + c;
            float m = g_stat2[j], rs = g_stat2[16 + j];
            a[j] = fmaxf(g2[j] * (vv[c] - m) * rs + be2[j], 0.f);
        }
    }
    float acc4 = cb4[0];
#pragma unroll
    for (int i = 0; i < 8; i++) {
        float acc = cb3[i];
#pragma unroll
        for (int j = 0; j < 16; j++) acc = fmaf(cW3[i * 16 + j], a[j], acc);
        acc = fmaxf(acc, 0.f);
        acc4 = fmaf(cW4[i], acc, acc4);
    }
    out[r] = 1.f / (1.f + expf(-acc4));
}

// ---------------------------------------------------------------------------
extern "C" void kernel_launch(void* const* d_in, const int* in_sizes, int n_in,
                              void* d_out, int out_size) {
    const float* x   = (const float*)d_in[0];
    const float* qw  = (const float*)d_in[1];
    const float* aW  = (const float*)d_in[2];
    const float* ab  = (const float*)d_in[3];
    const float* fW1 = (const float*)d_in[4];
    const float* fb1 = (const float*)d_in[5];
    const float* fW2 = (const float*)d_in[6];
    const float* fb2 = (const float*)d_in[7];
    const float* cW1 = (const float*)d_in[8];
    const float* cb1 = (const float*)d_in[9];
    const float* g1  = (const float*)d_in[10];
    const float* be1 = (const float*)d_in[11];
    const float* cW2 = (const float*)d_in[12];
    const float* cb2 = (const float*)d_in[13];
    const float* g2  = (const float*)d_in[14];
    const float* be2 = (const float*)d_in[15];
    const float* cW3 = (const float*)d_in[16];
    const float* cb3 = (const float*)d_in[17];
    const float* cW4 = (const float*)d_in[18];
    const float* cb4 = (const float*)d_in[19];
    float* out = (float*)d_out;

    prep_kernel<<<1, 256>>>(qw, fW1);
    qnn_kernel<<<BATCH / 8, 256>>>(x, aW, ab, fb1, fW2, fb2, cW1, cb1);
    stats1_kernel<<<1, 1024>>>();
    bn1_kernel<<<BATCH / 256, 256>>>(g1, be1, cW2, cb2);
    stats2_kernel<<<1, 1024>>>();
    final_kernel<<<BATCH / 256, 256>>>(g2, be2, cW3, cb3, cW4, cb4, out);
}

// round 4
// speedup vs baseline: 2.7693x; 2.7693x over previous
#include <cuda_runtime.h>
#include <math.h>

#define BATCH 8192
#define FULL 0xffffffffu
#define RB 16                      // rows per block in main GEMM
#define NBLK (BATCH / RB)          // 512
#define BN1_T 128
#define BN1_B (BATCH / BN1_T)      // 64

// Scratch (no allocation allowed -> device globals)
__device__ float2 g_Wri[256 * 256];   // [k][a] = (Ur[a][k], Ui[a][k])   512KB
__device__ float  g_Wf[256 * 64];     // [k][c] = fW1[c][k]
__device__ float  g_h1[BATCH * 32];
__device__ float  g_h2[BATCH * 16];
__device__ float  g_part1[NBLK * 64]; // per-block: sum[32], sumsq[32]
__device__ float  g_part2[BN1_B * 32];// per-block: sum[16], sumsq[16]
__device__ float  g_stat1[64];        // mean[32], rstd[32]
__device__ float  g_stat2[32];        // mean[16], rstd[16]

// ---------------------------------------------------------------------------
// packed f32x2 helpers (sm_100+/sm_103a)
// ---------------------------------------------------------------------------
#define PACK2(d, v) asm("mov.b64 %0,{%1,%1};" : "=l"(d) : "f"(v))
#define FMA2(acc, a, b) \
    asm("fma.rn.f32x2 %0,%1,%2,%0;" : "+l"(acc) : "l"(a), "l"(b))
#define UNPK(lo, hi, v) asm("mov.b64 {%0,%1},%2;" : "=f"(lo), "=f"(hi) : "l"(v))

// ---------------------------------------------------------------------------
// CNOT helpers (state: sr[8]/si[8] per lane; lane = amp bits 7..3)
// ---------------------------------------------------------------------------
#define CNOT_LL(cm, tm)                                                        \
    {                                                                          \
        _Pragma("unroll") for (int j = 0; j < 8; j++) {                        \
            float orr = __shfl_xor_sync(FULL, sr[j], (tm));                    \
            float ori = __shfl_xor_sync(FULL, si[j], (tm));                    \
            if (lane & (cm)) { sr[j] = orr; si[j] = ori; }                     \
        }                                                                      \
    }

#define CNOT_LT(cm, mb)                                                        \
    {                                                                          \
        bool f = (lane & (cm)) != 0;                                           \
        _Pragma("unroll") for (int j = 0; j < 8; j++) {                        \
            if (j & (mb)) continue;                                            \
            int j1 = j | (mb);                                                 \
            float t0r = sr[j], t0i = si[j];                                    \
            sr[j] = f ? sr[j1] : sr[j];                                        \
            si[j] = f ? si[j1] : si[j];                                        \
            sr[j1] = f ? t0r : sr[j1];                                         \
            si[j1] = f ? t0i : si[j1];                                         \
        }                                                                      \
    }

#define CNOT_TL(mb, tm)                                                        \
    {                                                                          \
        _Pragma("unroll") for (int j = 0; j < 8; j++) {                        \
            if (!(j & (mb))) continue;                                         \
            sr[j] = __shfl_xor_sync(FULL, sr[j], (tm));                        \
            si[j] = __shfl_xor_sync(FULL, si[j], (tm));                        \
        }                                                                      \
    }

#define CNOT_TT(cmb, tmb)                                                      \
    {                                                                          \
        _Pragma("unroll") for (int j = 0; j < 8; j++) {                        \
            if (!((j & (cmb)) && !(j & (tmb)))) continue;                      \
            int j1 = j | (tmb);                                                \
            float tr = sr[j]; sr[j] = sr[j1]; sr[j1] = tr;                     \
            float ti = si[j]; si[j] = si[j1]; si[j1] = ti;                     \
        }                                                                      \
    }

// ---------------------------------------------------------------------------
// Prep: blocks 0..31 compute the circuit unitary U column-by-column
// (warp w of block b simulates basis state e_{b*8+w}); block 32 transposes fW1.
// ---------------------------------------------------------------------------
__global__ void __launch_bounds__(256) prep_kernel(const float* __restrict__ qw,
                                                   const float* __restrict__ fW1) {
    int t = threadIdx.x;
    if (blockIdx.x == 32) {
        for (int idx = t; idx < 64 * 256; idx += 256) {
            int c = idx >> 8, k = idx & 255;
            g_Wf[k * 64 + c] = fW1[idx];
        }
        return;
    }

    __shared__ float s_U[48 * 8];
    if (t < 48) {
        int l = t / 8, q = t % 8;
        float ax = qw[l * 24 + 3 * q + 0] * 0.5f;
        float ay = qw[l * 24 + 3 * q + 1] * 0.5f;
        float az = qw[l * 24 + 3 * q + 2] * 0.5f;
        float cx, sx, cy, sy, cz, sz;
        sincosf(ax, &sx, &cx);
        sincosf(ay, &sy, &cy);
        sincosf(az, &sz, &cz);
        float m00r = cy * cx, m00i = sy * sx;
        float m01r = -sy * cx, m01i = -cy * sx;
        float m10r = sy * cx, m10i = -cy * sx;
        float m11r = cy * cx, m11i = -sy * sx;
        float* u = &s_U[t * 8];
        u[0] = cz * m00r + sz * m00i;  u[1] = cz * m00i - sz * m00r;
        u[2] = cz * m01r + sz * m01i;  u[3] = cz * m01i - sz * m01r;
        u[4] = cz * m10r - sz * m10i;  u[5] = cz * m10i + sz * m10r;
        u[6] = cz * m11r - sz * m11i;  u[7] = cz * m11i + sz * m11r;
    }
    __syncthreads();

    int lane = t & 31;
    int wid = t >> 5;
    int kcol = blockIdx.x * 8 + wid;

    float sr[8], si[8];
#pragma unroll
    for (int j = 0; j < 8; j++) {
        sr[j] = (lane * 8 + j == kcol) ? 1.f : 0.f;
        si[j] = 0.f;
    }

#pragma unroll 1
    for (int l = 0; l < 6; l++) {
        const float* Ul = &s_U[l * 64];
        for (int q = 0; q < 5; q++) {
            const float* u = &Ul[q * 8];
            int m = 16 >> q;
            bool hi = (lane & m) != 0;
            float csr = hi ? u[6] : u[0], csi = hi ? u[7] : u[1];
            float cor = hi ? u[4] : u[2], coi = hi ? u[5] : u[3];
#pragma unroll
            for (int j = 0; j < 8; j++) {
                float orr = __shfl_xor_sync(FULL, sr[j], m);
                float ori = __shfl_xor_sync(FULL, si[j], m);
                float nr = csr * sr[j] - csi * si[j] + cor * orr - coi * ori;
                float ni = csr * si[j] + csi * sr[j] + cor * ori + coi * orr;
                sr[j] = nr; si[j] = ni;
            }
        }
#pragma unroll
        for (int q = 5; q < 8; q++) {
            const float* u = &Ul[q * 8];
            int mb = 1 << (7 - q);
#pragma unroll
            for (int j = 0; j < 8; j++) {
                if (j & mb) continue;
                int j1 = j | mb;
                float ar = sr[j], ai = si[j], br = sr[j1], bi = si[j1];
                sr[j]  = u[0] * ar - u[1] * ai + u[2] * br - u[3] * bi;
                si[j]  = u[0] * ai + u[1] * ar + u[2] * bi + u[3] * br;
                sr[j1] = u[4] * ar - u[5] * ai + u[6] * br - u[7] * bi;
                si[j1] = u[4] * ai + u[5] * ar + u[6] * bi + u[7] * br;
            }
        }
        CNOT_LL(16, 8);
        CNOT_LL(8, 4);
        CNOT_LL(4, 2);
        CNOT_LL(2, 1);
        CNOT_LT(1, 4);
        CNOT_TT(4, 2);
        CNOT_TT(2, 1);
        CNOT_TL(1, 16);
        CNOT_LL(16, 4);
        CNOT_LL(4, 1);
        CNOT_LT(1, 2);
    }

    // column kcol of U: amplitude a = lane*8 + j
#pragma unroll
    for (int j = 0; j < 8; j++)
        g_Wri[kcol * 256 + lane * 8 + j] = make_float2(sr[j], si[j]);
}

// ---------------------------------------------------------------------------
// Main fused kernel: GEMM x@[Ur|Ui|fW1^T] + quantum epilogue + adapter +
// feature head + cW1, writes g_h1 and per-block BN1 partial sums.
// Block = 256 threads, RB=16 rows.
// ---------------------------------------------------------------------------
__global__ void __launch_bounds__(256, 2) main_kernel(
    const float* __restrict__ x,
    const float* __restrict__ aW, const float* __restrict__ ab,
    const float* __restrict__ fb1,
    const float* __restrict__ fW2, const float* __restrict__ fb2,
    const float* __restrict__ cW1, const float* __restrict__ cb1)
{
    __shared__ __align__(16) float xs[256 * RB];   // transposed [k][r]
    __shared__ float s0s[8][RB], s1s[8][RB], fvs[8][RB];
    __shared__ float zs[RB][4], cfs[RB][4], hs[RB][4];
    __shared__ float ps[32][8], ps2[32][8];

    int t = threadIdx.x;
    int base = blockIdx.x * RB;

    // coalesced load of 16 rows of x, store transposed [k][r]
    const float4* xg = (const float4*)(x + base * 256);
#pragma unroll
    for (int i = 0; i < 4; i++) {
        int g = t + 256 * i;          // float4 index over 16x256
        float4 v = xg[g];
        int r = g >> 6;
        int k4 = (g & 63) * 4;
        xs[(k4 + 0) * RB + r] = v.x;
        xs[(k4 + 1) * RB + r] = v.y;
        xs[(k4 + 2) * RB + r] = v.z;
        xs[(k4 + 3) * RB + r] = v.w;
    }
    __syncthreads();

    unsigned long long accR[8], accI[8], accF[8];
#pragma unroll
    for (int p = 0; p < 8; p++) { accR[p] = 0ull; accI[p] = 0ull; accF[p] = 0ull; }

    int fc = t & 63;
#pragma unroll 4
    for (int k = 0; k < 256; k++) {
        float2 w = g_Wri[k * 256 + t];
        float wf = g_Wf[k * 64 + fc];
        unsigned long long wr2, wi2, wf2;
        PACK2(wr2, w.x);
        PACK2(wi2, w.y);
        PACK2(wf2, wf);
        const ulonglong2* xp = (const ulonglong2*)(xs + k * RB);
        ulonglong2 q0 = xp[0], q1 = xp[1], q2 = xp[2], q3 = xp[3];
        unsigned long long xv[8] = {q0.x, q0.y, q1.x, q1.y, q2.x, q2.y, q3.x, q3.y};
#pragma unroll
        for (int p = 0; p < 8; p++) {
            FMA2(accR[p], wr2, xv[p]);
            FMA2(accI[p], wi2, xv[p]);
            FMA2(accF[p], wf2, xv[p]);
        }
    }

    // unpack: prob[r] for output col a=t ; feature contribution for col fc
    int lane = t & 31;
    int wid = t >> 5;
    float prob[RB], fcon[RB];
    float fb = fb1[fc];
    float w2 = fW2[(wid >> 1) * 64 + fc];
#pragma unroll
    for (int p = 0; p < 8; p++) {
        float r0, r1, i0, i1, f0, f1;
        UNPK(r0, r1, accR[p]);
        UNPK(i0, i1, accI[p]);
        UNPK(f0, f1, accF[p]);
        prob[2 * p]     = r0 * r0 + i0 * i0;
        prob[2 * p + 1] = r1 * r1 + i1 * i1;
        fcon[2 * p]     = fmaxf(f0 + fb, 0.f) * w2;
        fcon[2 * p + 1] = fmaxf(f1 + fb, 0.f) * w2;
    }

    float sgn = (lane & 16) ? -1.f : 1.f;
#pragma unroll
    for (int r = 0; r < RB; r++) {
        float a = prob[r], b = sgn * prob[r], c = fcon[r];
#pragma unroll
        for (int o = 16; o; o >>= 1) {
            a += __shfl_xor_sync(FULL, a, o);
            b += __shfl_xor_sync(FULL, b, o);
            c += __shfl_xor_sync(FULL, c, o);
        }
        if (lane == 0) { s0s[wid][r] = a; s1s[wid][r] = b; fvs[wid][r] = c; }
    }
    __syncthreads();

    // z expectations + feature head
    if (t < 64) {
        int r = t & 15, i = t >> 4;
        float S = 0.f, acc = 0.f;
        if (i < 3) {
#pragma unroll
            for (int w = 0; w < 8; w++) {
                float v = s0s[w][r];
                S += v;
                acc += ((w >> (2 - i)) & 1) ? -v : v;
            }
        } else {
#pragma unroll
            for (int w = 0; w < 8; w++) {
                S += s0s[w][r];
                acc += s1s[w][r];
            }
        }
        zs[r][i] = acc / S;
        cfs[r][i] = tanhf(fvs[2 * i][r] + fvs[2 * i + 1][r] + fb2[i]);
    }
    __syncthreads();
    if (t < 64) {
        int r = t & 15, i = t >> 4;
        hs[r][i] = ab[i] + aW[i * 4 + 0] * zs[r][0] + aW[i * 4 + 1] * zs[r][1]
                         + aW[i * 4 + 2] * zs[r][2] + aW[i * 4 + 3] * zs[r][3]
                 + cfs[r][i];
    }
    __syncthreads();

    // cW1 -> g_h1 + BN1 block partials
    {
        int j = t & 31, rg = t >> 5;
        float4 w1 = ((const float4*)cW1)[j];
        float bj = cb1[j];
        float s = 0.f, s2 = 0.f;
#pragma unroll
        for (int rr = rg; rr < RB; rr += 8) {
            float v = bj + w1.x * hs[rr][0] + w1.y * hs[rr][1]
                         + w1.z * hs[rr][2] + w1.w * hs[rr][3];
            g_h1[(base + rr) * 32 + j] = v;
            s += v;
            s2 += v * v;
        }
        ps[j][rg] = s;
        ps2[j][rg] = s2;
    }
    __syncthreads();
    if (t < 32) {
        float a = 0.f, b = 0.f;
#pragma unroll
        for (int g = 0; g < 8; g++) { a += ps[t][g]; b += ps2[t][g]; }
        g_part1[blockIdx.x * 64 + t] = a;
        g_part1[blockIdx.x * 64 + 32 + t] = b;
    }
}

// ---------------------------------------------------------------------------
// Deterministic stat combiners
// ---------------------------------------------------------------------------
__global__ void combine1_kernel() {
    int t = threadIdx.x;
    if (t < 32) {
        double s = 0.0, s2 = 0.0;
        for (int b = 0; b < NBLK; b++) {
            s  += g_part1[b * 64 + t];
            s2 += g_part1[b * 64 + 32 + t];
        }
        double mean = s / BATCH;
        double var = s2 / BATCH - mean * mean;
        g_stat1[t] = (float)mean;
        g_stat1[32 + t] = rsqrtf((float)var + 1e-5f);
    }
}

__global__ void combine2_kernel() {
    int t = threadIdx.x;
    if (t < 16) {
        double s = 0.0, s2 = 0.0;
        for (int b = 0; b < BN1_B; b++) {
            s  += g_part2[b * 32 + t];
            s2 += g_part2[b * 32 + 16 + t];
        }
        double mean = s / BATCH;
        double var = s2 / BATCH - mean * mean;
        g_stat2[t] = (float)mean;
        g_stat2[16 + t] = rsqrtf((float)var + 1e-5f);
    }
}

// ---------------------------------------------------------------------------
// BN1 + relu + cW2 -> g_h2 + BN2 block partials. Thread per row, 128/block.
// ---------------------------------------------------------------------------
__global__ void __launch_bounds__(BN1_T) bn1_kernel(
    const float* __restrict__ g1, const float* __restrict__ be1,
    const float* __restrict__ cW2, const float* __restrict__ cb2)
{
    __shared__ float sw[4][16], sw2[4][16];
    int r = blockIdx.x * BN1_T + threadIdx.x;
    float a[32];
    const float4* hp = (const float4*)&g_h1[r * 32];
#pragma unroll
    for (int j4 = 0; j4 < 8; j4++) {
        float4 v = hp[j4];
        float vv[4] = {v.x, v.y, v.z, v.w};
#pragma unroll
        for (int c = 0; c < 4; c++) {
            int j = j4 * 4 + c;
            a[j] = fmaxf(g1[j] * (vv[c] - g_stat1[j]) * g_stat1[32 + j] + be1[j], 0.f);
        }
    }
    float ov[16];
#pragma unroll
    for (int i = 0; i < 16; i++) {
        float acc = cb2[i];
#pragma unroll
        for (int j = 0; j < 32; j++) acc = fmaf(cW2[i * 32 + j], a[j], acc);
        ov[i] = acc;
    }
#pragma unroll
    for (int i4 = 0; i4 < 4; i4++)
        ((float4*)&g_h2[r * 16])[i4] =
            make_float4(ov[i4 * 4], ov[i4 * 4 + 1], ov[i4 * 4 + 2], ov[i4 * 4 + 3]);

    // partials (fixed-order warp trees -> deterministic)
    int lane = threadIdx.x & 31, w = threadIdx.x >> 5;
#pragma unroll
    for (int f = 0; f < 16; f++) {
        float s = ov[f], q = ov[f] * ov[f];
#pragma unroll
        for (int o = 16; o; o >>= 1) {
            s += __shfl_xor_sync(FULL, s, o);
            q += __shfl_xor_sync(FULL, q, o);
        }
        if (lane == 0) { sw[w][f] = s; sw2[w][f] = q; }
    }
    __syncthreads();
    if (threadIdx.x < 32) {
        int f = threadIdx.x & 15, kind = threadIdx.x >> 4;
        float s = 0.f;
#pragma unroll
        for (int ww = 0; ww < 4; ww++) s += kind ? sw2[ww][f] : sw[ww][f];
        g_part2[blockIdx.x * 32 + kind * 16 + f] = s;
    }
}

// ---------------------------------------------------------------------------
// BN2 + relu + cW3 + relu + cW4 + sigmoid -> out. Thread per row, 128/block.
// ---------------------------------------------------------------------------
__global__ void __launch_bounds__(BN1_T) final_kernel(
    const float* __restrict__ g2, const float* __restrict__ be2,
    const float* __restrict__ cW3, const float* __restrict__ cb3,
    const float* __restrict__ cW4, const float* __restrict__ cb4,
    float* __restrict__ out)
{
    int r = blockIdx.x * BN1_T + threadIdx.x;
    float a[16];
    const float4* hp = (const float4*)&g_h2[r * 16];
#pragma unroll
    for (int j4 = 0; j4 < 4; j4++) {
        float4 v = hp[j4];
        float vv[4] = {v.x, v.y, v.z, v.w};
#pragma unroll
        for (int c = 0; c < 4; c++) {
            int j = j4 * 4 + c;
            a[j] = fmaxf(g2[j] * (vv[c] - g_stat2[j]) * g_stat2[16 + j] + be2[j], 0.f);
        }
    }
    float acc4 = cb4[0];
#pragma unroll
    for (int i = 0; i < 8; i++) {
        float acc = cb3[i];
#pragma unroll
        for (int j = 0; j < 16; j++) acc = fmaf(cW3[i * 16 + j], a[j], acc);
        acc = fmaxf(acc, 0.f);
        acc4 = fmaf(cW4[i], acc, acc4);
    }
    out[r] = 1.f / (1.f + expf(-acc4));
}

// ---------------------------------------------------------------------------
extern "C" void kernel_launch(void* const* d_in, const int* in_sizes, int n_in,
                              void* d_out, int out_size) {
    const float* x   = (const float*)d_in[0];
    const float* qw  = (const float*)d_in[1];
    const float* aW  = (const float*)d_in[2];
    const float* ab  = (const float*)d_in[3];
    const float* fW1 = (const float*)d_in[4];
    const float* fb1 = (const float*)d_in[5];
    const float* fW2 = (const float*)d_in[6];
    const float* fb2 = (const float*)d_in[7];
    const float* cW1 = (const float*)d_in[8];
    const float* cb1 = (const float*)d_in[9];
    const float* g1  = (const float*)d_in[10];
    const float* be1 = (const float*)d_in[11];
    const float* cW2 = (const float*)d_in[12];
    const float* cb2 = (const float*)d_in[13];
    const float* g2  = (const float*)d_in[14];
    const float* be2 = (const float*)d_in[15];
    const float* cW3 = (const float*)d_in[16];
    const float* cb3 = (const float*)d_in[17];
    const float* cW4 = (const float*)d_in[18];
    const float* cb4 = (const float*)d_in[19];
    float* out = (float*)d_out;

    prep_kernel<<<33, 256>>>(qw, fW1);
    main_kernel<<<NBLK, 256>>>(x, aW, ab, fb1, fW2, fb2, cW1, cb1);
    combine1_kernel<<<1, 32>>>();
    bn1_kernel<<<BN1_B, BN1_T>>>(g1, be1, cW2, cb2);
    combine2_kernel<<<1, 16>>>();
    final_kernel<<<BN1_B, BN1_T>>>(g2, be2, cW3, cb3, cW4, cb4, out);
}

// round 8
// speedup vs baseline: 3.1409x; 1.1342x over previous
#include <cuda_runtime.h>
#include <math.h>

#define BATCH 8192
#define FULL 0xffffffffu
#define RB 32                      // rows per block in main GEMM
#define NBLK (BATCH / RB)          // 256
#define BN_B (BATCH / 32)          // 256 blocks of 32 threads for bn1/final

// Scratch (no allocation allowed -> device globals)
__device__ float2 g_Wri[256 * 256];   // [k][a] = (Ur[a][k], Ui[a][k])   512KB
__device__ float  g_Wf[256 * 64];     // [k][c] = fW1[c][k]
__device__ float  g_h1[BATCH * 32];
__device__ float  g_h2[BATCH * 16];
__device__ float  g_part1[NBLK * 64]; // per-block: sum[32], sumsq[32]
__device__ float  g_part2[BN_B * 32]; // per-block: sum[16], sumsq[16]
__device__ float  g_stat1[64];        // mean[32], rstd[32]
__device__ float  g_stat2[32];        // mean[16], rstd[16]

// ---------------------------------------------------------------------------
// packed f32x2 helpers (sm_100+/sm_103a)
// ---------------------------------------------------------------------------
#define PACK2(d, v) asm("mov.b64 %0,{%1,%1};" : "=l"(d) : "f"(v))
#define FMA2(acc, a, b) \
    asm("fma.rn.f32x2 %0,%1,%2,%0;" : "+l"(acc) : "l"(a), "l"(b))
#define UNPK(lo, hi, v) asm("mov.b64 {%0,%1},%2;" : "=f"(lo), "=f"(hi) : "l"(v))

// ---------------------------------------------------------------------------
// CNOT helpers (state: sr[8]/si[8] per lane; lane = amp bits 7..3)
// ---------------------------------------------------------------------------
#define CNOT_LL(cm, tm)                                                        \
    {                                                                          \
        _Pragma("unroll") for (int j = 0; j < 8; j++) {                        \
            float orr = __shfl_xor_sync(FULL, sr[j], (tm));                    \
            float ori = __shfl_xor_sync(FULL, si[j], (tm));                    \
            if (lane & (cm)) { sr[j] = orr; si[j] = ori; }                     \
        }                                                                      \
    }

#define CNOT_LT(cm, mb)                                                        \
    {                                                                          \
        bool f = (lane & (cm)) != 0;                                           \
        _Pragma("unroll") for (int j = 0; j < 8; j++) {                        \
            if (j & (mb)) continue;                                            \
            int j1 = j | (mb);                                                 \
            float t0r = sr[j], t0i = si[j];                                    \
            sr[j] = f ? sr[j1] : sr[j];                                        \
            si[j] = f ? si[j1] : si[j];                                        \
            sr[j1] = f ? t0r : sr[j1];                                         \
            si[j1] = f ? t0i : si[j1];                                         \
        }                                                                      \
    }

#define CNOT_TL(mb, tm)                                                        \
    {                                                                          \
        _Pragma("unroll") for (int j = 0; j < 8; j++) {                        \
            if (!(j & (mb))) continue;                                         \
            sr[j] = __shfl_xor_sync(FULL, sr[j], (tm));                        \
            si[j] = __shfl_xor_sync(FULL, si[j], (tm));                        \
        }                                                                      \
    }

#define CNOT_TT(cmb, tmb)                                                      \
    {                                                                          \
        _Pragma("unroll") for (int j = 0; j < 8; j++) {                        \
            if (!((j & (cmb)) && !(j & (tmb)))) continue;                      \
            int j1 = j | (tmb);                                                \
            float tr = sr[j]; sr[j] = sr[j1]; sr[j1] = tr;                     \
            float ti = si[j]; si[j] = si[j1]; si[j1] = ti;                     \
        }                                                                      \
    }

// ---------------------------------------------------------------------------
// Prep: blocks 0..31 compute the circuit unitary U column-by-column
// (warp w of block b simulates basis state e_{b*8+w}); block 32 transposes fW1.
// ---------------------------------------------------------------------------
__global__ void __launch_bounds__(256) prep_kernel(const float* __restrict__ qw,
                                                   const float* __restrict__ fW1) {
    int t = threadIdx.x;
    if (blockIdx.x == 32) {
        for (int idx = t; idx < 64 * 256; idx += 256) {
            int c = idx >> 8, k = idx & 255;
            g_Wf[k * 64 + c] = fW1[idx];
        }
        return;
    }

    __shared__ float s_U[48 * 8];
    if (t < 48) {
        int l = t / 8, q = t % 8;
        float ax = qw[l * 24 + 3 * q + 0] * 0.5f;
        float ay = qw[l * 24 + 3 * q + 1] * 0.5f;
        float az = qw[l * 24 + 3 * q + 2] * 0.5f;
        float cx, sx, cy, sy, cz, sz;
        sincosf(ax, &sx, &cx);
        sincosf(ay, &sy, &cy);
        sincosf(az, &sz, &cz);
        float m00r = cy * cx, m00i = sy * sx;
        float m01r = -sy * cx, m01i = -cy * sx;
        float m10r = sy * cx, m10i = -cy * sx;
        float m11r = cy * cx, m11i = -sy * sx;
        float* u = &s_U[t * 8];
        u[0] = cz * m00r + sz * m00i;  u[1] = cz * m00i - sz * m00r;
        u[2] = cz * m01r + sz * m01i;  u[3] = cz * m01i - sz * m01r;
        u[4] = cz * m10r - sz * m10i;  u[5] = cz * m10i + sz * m10r;
        u[6] = cz * m11r - sz * m11i;  u[7] = cz * m11i + sz * m11r;
    }
    __syncthreads();

    int lane = t & 31;
    int wid = t >> 5;
    int kcol = blockIdx.x * 8 + wid;

    float sr[8], si[8];
#pragma unroll
    for (int j = 0; j < 8; j++) {
        sr[j] = (lane * 8 + j == kcol) ? 1.f : 0.f;
        si[j] = 0.f;
    }

#pragma unroll 1
    for (int l = 0; l < 6; l++) {
        const float* Ul = &s_U[l * 64];
        for (int q = 0; q < 5; q++) {
            const float* u = &Ul[q * 8];
            int m = 16 >> q;
            bool hi = (lane & m) != 0;
            float csr = hi ? u[6] : u[0], csi = hi ? u[7] : u[1];
            float cor = hi ? u[4] : u[2], coi = hi ? u[5] : u[3];
#pragma unroll
            for (int j = 0; j < 8; j++) {
                float orr = __shfl_xor_sync(FULL, sr[j], m);
                float ori = __shfl_xor_sync(FULL, si[j], m);
                float nr = csr * sr[j] - csi * si[j] + cor * orr - coi * ori;
                float ni = csr * si[j] + csi * sr[j] + cor * ori + coi * orr;
                sr[j] = nr; si[j] = ni;
            }
        }
#pragma unroll
        for (int q = 5; q < 8; q++) {
            const float* u = &Ul[q * 8];
            int mb = 1 << (7 - q);
#pragma unroll
            for (int j = 0; j < 8; j++) {
                if (j & mb) continue;
                int j1 = j | mb;
                float ar = sr[j], ai = si[j], br = sr[j1], bi = si[j1];
                sr[j]  = u[0] * ar - u[1] * ai + u[2] * br - u[3] * bi;
                si[j]  = u[0] * ai + u[1] * ar + u[2] * bi + u[3] * br;
                sr[j1] = u[4] * ar - u[5] * ai + u[6] * br - u[7] * bi;
                si[j1] = u[4] * ai + u[5] * ar + u[6] * bi + u[7] * br;
            }
        }
        CNOT_LL(16, 8);
        CNOT_LL(8, 4);
        CNOT_LL(4, 2);
        CNOT_LL(2, 1);
        CNOT_LT(1, 4);
        CNOT_TT(4, 2);
        CNOT_TT(2, 1);
        CNOT_TL(1, 16);
        CNOT_LL(16, 4);
        CNOT_LL(4, 1);
        CNOT_LT(1, 2);
    }

#pragma unroll
    for (int j = 0; j < 8; j++)
        g_Wri[kcol * 256 + lane * 8 + j] = make_float2(sr[j], si[j]);
}

// ---------------------------------------------------------------------------
// Main fused kernel: GEMM x@[Ur|Ui|fW1^T] + quantum epilogue + adapter +
// feature head + cW1, writes g_h1 and per-block BN1 partial sums.
// Block = 256 threads, RB=32 rows (halves weight re-read traffic vs RB=16).
// ---------------------------------------------------------------------------
__global__ void __launch_bounds__(256) main_kernel(
    const float* __restrict__ x,
    const float* __restrict__ aW, const float* __restrict__ ab,
    const float* __restrict__ fb1,
    const float* __restrict__ fW2, const float* __restrict__ fb2,
    const float* __restrict__ cW1, const float* __restrict__ cb1)
{
    __shared__ __align__(16) float xs[256 * RB];   // transposed [k][r]  32KB
    __shared__ float s0s[8][RB], s1s[8][RB], fvs[8][RB];
    __shared__ float zs[RB][4], cfs[RB][4], hs[RB][4];
    __shared__ float ps[32][8], ps2[32][8];

    int t = threadIdx.x;
    int base = blockIdx.x * RB;

    // coalesced load of RB rows of x, store transposed [k][r]
    const float4* xg = (const float4*)(x + base * 256);
#pragma unroll
    for (int i = 0; i < (RB * 64) / 256; i++) {
        int g = t + 256 * i;          // float4 index over RBx256
        float4 v = xg[g];
        int r = g >> 6;
        int k4 = (g & 63) * 4;
        xs[(k4 + 0) * RB + r] = v.x;
        xs[(k4 + 1) * RB + r] = v.y;
        xs[(k4 + 2) * RB + r] = v.z;
        xs[(k4 + 3) * RB + r] = v.w;
    }
    __syncthreads();

    unsigned long long accR[RB / 2], accI[RB / 2], accF[RB / 2];
#pragma unroll
    for (int p = 0; p < RB / 2; p++) { accR[p] = 0ull; accI[p] = 0ull; accF[p] = 0ull; }

    int fc = t & 63;
#pragma unroll 2
    for (int k = 0; k < 256; k++) {
        float2 w = g_Wri[k * 256 + t];
        float wf = g_Wf[k * 64 + fc];
        unsigned long long wr2, wi2, wf2;
        PACK2(wr2, w.x);
        PACK2(wi2, w.y);
        PACK2(wf2, wf);
        const ulonglong2* xp = (const ulonglong2*)(xs + k * RB);
#pragma unroll
        for (int q = 0; q < RB / 4; q++) {
            ulonglong2 xv = xp[q];
            FMA2(accR[2 * q], wr2, xv.x);
            FMA2(accI[2 * q], wi2, xv.x);
            FMA2(accF[2 * q], wf2, xv.x);
            FMA2(accR[2 * q + 1], wr2, xv.y);
            FMA2(accI[2 * q + 1], wi2, xv.y);
            FMA2(accF[2 * q + 1], wf2, xv.y);
        }
    }

    // unpack: prob[r] for output col a=t ; feature contribution for col fc
    int lane = t & 31;
    int wid = t >> 5;
    float prob[RB], fcon[RB];
    float fb = fb1[fc];
    float w2 = fW2[(wid >> 1) * 64 + fc];
#pragma unroll
    for (int p = 0; p < RB / 2; p++) {
        float r0, r1, i0, i1, f0, f1;
        UNPK(r0, r1, accR[p]);
        UNPK(i0, i1, accI[p]);
        UNPK(f0, f1, accF[p]);
        prob[2 * p]     = r0 * r0 + i0 * i0;
        prob[2 * p + 1] = r1 * r1 + i1 * i1;
        fcon[2 * p]     = fmaxf(f0 + fb, 0.f) * w2;
        fcon[2 * p + 1] = fmaxf(f1 + fb, 0.f) * w2;
    }

    float sgn = (lane & 16) ? -1.f : 1.f;
#pragma unroll
    for (int r = 0; r < RB; r++) {
        float a = prob[r], b = sgn * prob[r], c = fcon[r];
#pragma unroll
        for (int o = 16; o; o >>= 1) {
            a += __shfl_xor_sync(FULL, a, o);
            b += __shfl_xor_sync(FULL, b, o);
            c += __shfl_xor_sync(FULL, c, o);
        }
        if (lane == 0) { s0s[wid][r] = a; s1s[wid][r] = b; fvs[wid][r] = c; }
    }
    __syncthreads();

    // z expectations + feature head (RB*4 = 128 threads)
    if (t < RB * 4) {
        int r = t & (RB - 1), i = t / RB;
        float S = 0.f, acc = 0.f;
        if (i < 3) {
#pragma unroll
            for (int w = 0; w < 8; w++) {
                float v = s0s[w][r];
                S += v;
                acc += ((w >> (2 - i)) & 1) ? -v : v;
            }
        } else {
#pragma unroll
            for (int w = 0; w < 8; w++) {
                S += s0s[w][r];
                acc += s1s[w][r];
            }
        }
        zs[r][i] = acc / S;
        cfs[r][i] = tanhf(fvs[2 * i][r] + fvs[2 * i + 1][r] + fb2[i]);
    }
    __syncthreads();
    if (t < RB * 4) {
        int r = t & (RB - 1), i = t / RB;
        hs[r][i] = ab[i] + aW[i * 4 + 0] * zs[r][0] + aW[i * 4 + 1] * zs[r][1]
                         + aW[i * 4 + 2] * zs[r][2] + aW[i * 4 + 3] * zs[r][3]
                 + cfs[r][i];
    }
    __syncthreads();

    // cW1 -> g_h1 + BN1 block partials
    {
        int j = t & 31, rg = t >> 5;
        float4 w1 = ((const float4*)cW1)[j];
        float bj = cb1[j];
        float s = 0.f, s2 = 0.f;
#pragma unroll
        for (int rr = rg; rr < RB; rr += 8) {
            float v = bj + w1.x * hs[rr][0] + w1.y * hs[rr][1]
                         + w1.z * hs[rr][2] + w1.w * hs[rr][3];
            g_h1[(base + rr) * 32 + j] = v;
            s += v;
            s2 += v * v;
        }
        ps[j][rg] = s;
        ps2[j][rg] = s2;
    }
    __syncthreads();
    if (t < 32) {
        float a = 0.f, b = 0.f;
#pragma unroll
        for (int g = 0; g < 8; g++) { a += ps[t][g]; b += ps2[t][g]; }
        g_part1[blockIdx.x * 64 + t] = a;
        g_part1[blockIdx.x * 64 + 32 + t] = b;
    }
}

// ---------------------------------------------------------------------------
// Deterministic parallel stat combiners (fixed-order fp64 trees)
// ---------------------------------------------------------------------------
__global__ void __launch_bounds__(1024) combine1_kernel() {
    int t = threadIdx.x;
    int f = t >> 5, lane = t & 31;         // 32 features x 32 lanes
    double s = 0.0, s2 = 0.0;
#pragma unroll
    for (int i = 0; i < NBLK / 32; i++) {  // 8 partial blocks per lane
        int b = lane + 32 * i;
        s  += (double)g_part1[b * 64 + f];
        s2 += (double)g_part1[b * 64 + 32 + f];
    }
#pragma unroll
    for (int o = 16; o; o >>= 1) {
        s  += __shfl_xor_sync(FULL, s, o);
        s2 += __shfl_xor_sync(FULL, s2, o);
    }
    if (lane == 0) {
        double mean = s / BATCH;
        double var = s2 / BATCH - mean * mean;
        g_stat1[f] = (float)mean;
        g_stat1[32 + f] = rsqrtf((float)var + 1e-5f);
    }
}

__global__ void __launch_bounds__(512) combine2_kernel() {
    int t = threadIdx.x;
    int f = t >> 5, lane = t & 31;         // 16 features x 32 lanes
    double s = 0.0, s2 = 0.0;
#pragma unroll
    for (int i = 0; i < BN_B / 32; i++) {  // 8 partial blocks per lane
        int b = lane + 32 * i;
        s  += (double)g_part2[b * 32 + f];
        s2 += (double)g_part2[b * 32 + 16 + f];
    }
#pragma unroll
    for (int o = 16; o; o >>= 1) {
        s  += __shfl_xor_sync(FULL, s, o);
        s2 += __shfl_xor_sync(FULL, s2, o);
    }
    if (lane == 0) {
        double mean = s / BATCH;
        double var = s2 / BATCH - mean * mean;
        g_stat2[f] = (float)mean;
        g_stat2[16 + f] = rsqrtf((float)var + 1e-5f);
    }
}

// ---------------------------------------------------------------------------
// BN1 + relu + cW2 -> g_h2 + BN2 block partials. 256 blocks x 32 threads.
// ---------------------------------------------------------------------------
__global__ void __launch_bounds__(32) bn1_kernel(
    const float* __restrict__ g1, const float* __restrict__ be1,
    const float* __restrict__ cW2, const float* __restrict__ cb2)
{
    int lane = threadIdx.x;
    int r = blockIdx.x * 32 + lane;
    float a[32];
    const float4* hp = (const float4*)&g_h1[r * 32];
#pragma unroll
    for (int j4 = 0; j4 < 8; j4++) {
        float4 v = hp[j4];
        float vv[4] = {v.x, v.y, v.z, v.w};
#pragma unroll
        for (int c = 0; c < 4; c++) {
            int j = j4 * 4 + c;
            a[j] = fmaxf(g1[j] * (vv[c] - g_stat1[j]) * g_stat1[32 + j] + be1[j], 0.f);
        }
    }
    float ov[16];
#pragma unroll
    for (int i = 0; i < 16; i++) {
        float acc = cb2[i];
#pragma unroll
        for (int j = 0; j < 32; j++) acc = fmaf(cW2[i * 32 + j], a[j], acc);
        ov[i] = acc;
    }
#pragma unroll
    for (int i4 = 0; i4 < 4; i4++)
        ((float4*)&g_h2[r * 16])[i4] =
            make_float4(ov[i4 * 4], ov[i4 * 4 + 1], ov[i4 * 4 + 2], ov[i4 * 4 + 3]);

    // per-block partials via fixed-order warp trees
    float outv = 0.f;
#pragma unroll
    for (int f = 0; f < 16; f++) {
        float s = ov[f], q = ov[f] * ov[f];
#pragma unroll
        for (int o = 16; o; o >>= 1) {
            s += __shfl_xor_sync(FULL, s, o);
            q += __shfl_xor_sync(FULL, q, o);
        }
        if (lane == f) outv = s;
        if (lane == f + 16) outv = q;
    }
    g_part2[blockIdx.x * 32 + lane] = outv;
}

// ---------------------------------------------------------------------------
// BN2 + relu + cW3 + relu + cW4 + sigmoid -> out. 256 blocks x 32 threads.
// ---------------------------------------------------------------------------
__global__ void __launch_bounds__(32) final_kernel(
    const float* __restrict__ g2, const float* __restrict__ be2,
    const float* __restrict__ cW3, const float* __restrict__ cb3,
    const float* __restrict__ cW4, const float* __restrict__ cb4,
    float* __restrict__ out)
{
    int r = blockIdx.x * 32 + threadIdx.x;
    float a[16];
    const float4* hp = (const float4*)&g_h2[r * 16];
#pragma unroll
    for (int j4 = 0; j4 < 4; j4++) {
        float4 v = hp[j4];
        float vv[4] = {v.x, v.y, v.z, v.w};
#pragma unroll
        for (int c = 0; c < 4; c++) {
            int j = j4 * 4 + c;
            a[j] = fmaxf(g2[j] * (vv[c] - g_stat2[j]) * g_stat2[16 + j] + be2[j], 0.f);
        }
    }
    float acc4 = cb4[0];
#pragma unroll
    for (int i = 0; i < 8; i++) {
        float acc = cb3[i];
#pragma unroll
        for (int j = 0; j < 16; j++) acc = fmaf(cW3[i * 16 + j], a[j], acc);
        acc = fmaxf(acc, 0.f);
        acc4 = fmaf(cW4[i], acc, acc4);
    }
    out[r] = 1.f / (1.f + expf(-acc4));
}

// ---------------------------------------------------------------------------
extern "C" void kernel_launch(void* const* d_in, const int* in_sizes, int n_in,
                              void* d_out, int out_size) {
    const float* x   = (const float*)d_in[0];
    const float* qw  = (const float*)d_in[1];
    const float* aW  = (const float*)d_in[2];
    const float* ab  = (const float*)d_in[3];
    const float* fW1 = (const float*)d_in[4];
    const float* fb1 = (const float*)d_in[5];
    const float* fW2 = (const float*)d_in[6];
    const float* fb2 = (const float*)d_in[7];
    const float* cW1 = (const float*)d_in[8];
    const float* cb1 = (const float*)d_in[9];
    const float* g1  = (const float*)d_in[10];
    const float* be1 = (const float*)d_in[11];
    const float* cW2 = (const float*)d_in[12];
    const float* cb2 = (const float*)d_in[13];
    const float* g2  = (const float*)d_in[14];
    const float* be2 = (const float*)d_in[15];
    const float* cW3 = (const float*)d_in[16];
    const float* cb3 = (const float*)d_in[17];
    const float* cW4 = (const float*)d_in[18];
    const float* cb4 = (const float*)d_in[19];
    float* out = (float*)d_out;

    prep_kernel<<<33, 256>>>(qw, fW1);
    main_kernel<<<NBLK, 256>>>(x, aW, ab, fb1, fW2, fb2, cW1, cb1);
    combine1_kernel<<<1, 1024>>>();
    bn1_kernel<<<BN_B, 32>>>(g1, be1, cW2, cb2);
    combine2_kernel<<<1, 512>>>();
    final_kernel<<<BN_B, 32>>>(g2, be2, cW3, cb3, cW4, cb4, out);
}

// round 10
// speedup vs baseline: 4.5342x; 1.4436x over previous
#include <cuda_runtime.h>
#include <math.h>

#define BATCH 8192
#define FULL 0xffffffffu
#define RB 32                      // rows per block in main GEMM
#define NBLK (BATCH / RB)          // 256

// Scratch (no allocation allowed -> device globals)
__device__ float2 g_Wri[256 * 256];   // [k][a] = (Ur[a][k], Ui[a][k])   512KB
__device__ float  g_Wf[256 * 64];     // [k][c] = fW1[c][k]
__device__ float  g_h[BATCH * 4];     // fused pre-cW1 hidden (qf+cf)
__device__ float  g_h2[BATCH * 16];
__device__ float  g_part1[NBLK * 16]; // per-block: 14 h-moments
__device__ float  g_part2[128 * 32];  // per-bn1-block: sum[16], sumsq[16]
__device__ float  g_stat1[64];        // mean1[32], rstd1[32]
__device__ float  g_stat2[32];        // mean2[16], rstd2[16]

// ---------------------------------------------------------------------------
// packed f32x2 helpers (sm_100+/sm_103a)
// ---------------------------------------------------------------------------
#define PACK2(d, v) asm("mov.b64 %0,{%1,%1};" : "=l"(d) : "f"(v))
#define FMA2(acc, a, b) \
    asm("fma.rn.f32x2 %0,%1,%2,%0;" : "+l"(acc) : "l"(a), "l"(b))
#define UNPK(lo, hi, v) asm("mov.b64 {%0,%1},%2;" : "=f"(lo), "=f"(hi) : "l"(v))

// ---------------------------------------------------------------------------
// CNOT helpers (state: sr[8]/si[8] per lane; lane = amp bits 7..3)
// ---------------------------------------------------------------------------
#define CNOT_LL(cm, tm)                                                        \
    {                                                                          \
        _Pragma("unroll") for (int j = 0; j < 8; j++) {                        \
            float orr = __shfl_xor_sync(FULL, sr[j], (tm));                    \
            float ori = __shfl_xor_sync(FULL, si[j], (tm));                    \
            if (lane & (cm)) { sr[j] = orr; si[j] = ori; }                     \
        }                                                                      \
    }

#define CNOT_LT(cm, mb)                                                        \
    {                                                                          \
        bool f = (lane & (cm)) != 0;                                           \
        _Pragma("unroll") for (int j = 0; j < 8; j++) {                        \
            if (j & (mb)) continue;                                            \
            int j1 = j | (mb);                                                 \
            float t0r = sr[j], t0i = si[j];                                    \
            sr[j] = f ? sr[j1] : sr[j];                                        \
            si[j] = f ? si[j1] : si[j];                                        \
            sr[j1] = f ? t0r : sr[j1];                                         \
            si[j1] = f ? t0i : si[j1];                                         \
        }                                                                      \
    }

#define CNOT_TL(mb, tm)                                                        \
    {                                                                          \
        _Pragma("unroll") for (int j = 0; j < 8; j++) {                        \
            if (!(j & (mb))) continue;                                         \
            sr[j] = __shfl_xor_sync(FULL, sr[j], (tm));                        \
            si[j] = __shfl_xor_sync(FULL, si[j], (tm));                        \
        }                                                                      \
    }

#define CNOT_TT(cmb, tmb)                                                      \
    {                                                                          \
        _Pragma("unroll") for (int j = 0; j < 8; j++) {                        \
            if (!((j & (cmb)) && !(j & (tmb)))) continue;                      \
            int j1 = j | (tmb);                                                \
            float tr = sr[j]; sr[j] = sr[j1]; sr[j1] = tr;                     \
            float ti = si[j]; si[j] = si[j1]; si[j1] = ti;                     \
        }                                                                      \
    }

// ---------------------------------------------------------------------------
// Prep: blocks 0..31 compute the circuit unitary U column-by-column;
// block 32 transposes fW1.
// ---------------------------------------------------------------------------
__global__ void __launch_bounds__(256) prep_kernel(const float* __restrict__ qw,
                                                   const float* __restrict__ fW1) {
    int t = threadIdx.x;
    if (blockIdx.x == 32) {
        for (int idx = t; idx < 64 * 256; idx += 256) {
            int c = idx >> 8, k = idx & 255;
            g_Wf[k * 64 + c] = fW1[idx];
        }
        return;
    }

    __shared__ float s_U[48 * 8];
    if (t < 48) {
        int l = t / 8, q = t % 8;
        float ax = qw[l * 24 + 3 * q + 0] * 0.5f;
        float ay = qw[l * 24 + 3 * q + 1] * 0.5f;
        float az = qw[l * 24 + 3 * q + 2] * 0.5f;
        float cx, sx, cy, sy, cz, sz;
        sincosf(ax, &sx, &cx);
        sincosf(ay, &sy, &cy);
        sincosf(az, &sz, &cz);
        float m00r = cy * cx, m00i = sy * sx;
        float m01r = -sy * cx, m01i = -cy * sx;
        float m10r = sy * cx, m10i = -cy * sx;
        float m11r = cy * cx, m11i = -sy * sx;
        float* u = &s_U[t * 8];
        u[0] = cz * m00r + sz * m00i;  u[1] = cz * m00i - sz * m00r;
        u[2] = cz * m01r + sz * m01i;  u[3] = cz * m01i - sz * m01r;
        u[4] = cz * m10r - sz * m10i;  u[5] = cz * m10i + sz * m10r;
        u[6] = cz * m11r - sz * m11i;  u[7] = cz * m11i + sz * m11r;
    }
    __syncthreads();

    int lane = t & 31;
    int wid = t >> 5;
    int kcol = blockIdx.x * 8 + wid;

    float sr[8], si[8];
#pragma unroll
    for (int j = 0; j < 8; j++) {
        sr[j] = (lane * 8 + j == kcol) ? 1.f : 0.f;
        si[j] = 0.f;
    }

#pragma unroll 1
    for (int l = 0; l < 6; l++) {
        const float* Ul = &s_U[l * 64];
        for (int q = 0; q < 5; q++) {
            const float* u = &Ul[q * 8];
            int m = 16 >> q;
            bool hi = (lane & m) != 0;
            float csr = hi ? u[6] : u[0], csi = hi ? u[7] : u[1];
            float cor = hi ? u[4] : u[2], coi = hi ? u[5] : u[3];
#pragma unroll
            for (int j = 0; j < 8; j++) {
                float orr = __shfl_xor_sync(FULL, sr[j], m);
                float ori = __shfl_xor_sync(FULL, si[j], m);
                float nr = csr * sr[j] - csi * si[j] + cor * orr - coi * ori;
                float ni = csr * si[j] + csi * sr[j] + cor * ori + coi * orr;
                sr[j] = nr; si[j] = ni;
            }
        }
#pragma unroll
        for (int q = 5; q < 8; q++) {
            const float* u = &Ul[q * 8];
            int mb = 1 << (7 - q);
#pragma unroll
            for (int j = 0; j < 8; j++) {
                if (j & mb) continue;
                int j1 = j | mb;
                float ar = sr[j], ai = si[j], br = sr[j1], bi = si[j1];
                sr[j]  = u[0] * ar - u[1] * ai + u[2] * br - u[3] * bi;
                si[j]  = u[0] * ai + u[1] * ar + u[2] * bi + u[3] * br;
                sr[j1] = u[4] * ar - u[5] * ai + u[6] * br - u[7] * bi;
                si[j1] = u[4] * ai + u[5] * ar + u[6] * bi + u[7] * br;
            }
        }
        CNOT_LL(16, 8);
        CNOT_LL(8, 4);
        CNOT_LL(4, 2);
        CNOT_LL(2, 1);
        CNOT_LT(1, 4);
        CNOT_TT(4, 2);
        CNOT_TT(2, 1);
        CNOT_TL(1, 16);
        CNOT_LL(16, 4);
        CNOT_LL(4, 1);
        CNOT_LT(1, 2);
    }

#pragma unroll
    for (int j = 0; j < 8; j++)
        g_Wri[kcol * 256 + lane * 8 + j] = make_float2(sr[j], si[j]);
}

// ---------------------------------------------------------------------------
// Main fused kernel: GEMM x@[Ur|Ui] (full) + x@fW1^T (row-partitioned, no
// redundancy) + quantum epilogue + adapter + feature head -> g_h + h-moments.
// 36 FMA2 per k per thread (was 48). 2 CTAs/SM.
// ---------------------------------------------------------------------------
__global__ void __launch_bounds__(256, 2) main_kernel(
    const float* __restrict__ x,
    const float* __restrict__ aW, const float* __restrict__ ab,
    const float* __restrict__ fb1,
    const float* __restrict__ fW2, const float* __restrict__ fb2)
{
    __shared__ __align__(16) float xs[256 * RB];   // transposed [k][r]  32KB
    __shared__ float s0s[8][RB], s1s[8][RB];
    __shared__ float fpart[8][4][8];               // [warp][i][local row]
    __shared__ float zs[RB][4], cfs[RB][4], hs[RB][4];

    int t = threadIdx.x;
    int base = blockIdx.x * RB;

    // coalesced load of RB rows of x, store transposed [k][r]
    const float4* xg = (const float4*)(x + base * 256);
#pragma unroll
    for (int i = 0; i < (RB * 64) / 256; i++) {
        int g = t + 256 * i;
        float4 v = xg[g];
        int r = g >> 6;
        int k4 = (g & 63) * 4;
        xs[(k4 + 0) * RB + r] = v.x;
        xs[(k4 + 1) * RB + r] = v.y;
        xs[(k4 + 2) * RB + r] = v.z;
        xs[(k4 + 3) * RB + r] = v.w;
    }
    __syncthreads();

    int fc = t & 63;
    int rg = t >> 6;       // row group (8 rows) this thread owns for feature

    unsigned long long accR[16], accI[16], accF[4];
#pragma unroll
    for (int p = 0; p < 16; p++) { accR[p] = 0ull; accI[p] = 0ull; }
#pragma unroll
    for (int p = 0; p < 4; p++) accF[p] = 0ull;

#pragma unroll 2
    for (int k = 0; k < 256; k++) {
        float2 w = g_Wri[k * 256 + t];
        float wf = g_Wf[k * 64 + fc];
        unsigned long long wr2, wi2, wf2;
        PACK2(wr2, w.x);
        PACK2(wi2, w.y);
        PACK2(wf2, wf);
        const ulonglong2* xp = (const ulonglong2*)(xs + k * RB);
        // feature rows (8rg .. 8rg+7)
        {
            ulonglong2 xfa = xp[2 * rg];
            ulonglong2 xfb = xp[2 * rg + 1];
            FMA2(accF[0], wf2, xfa.x);
            FMA2(accF[1], wf2, xfa.y);
            FMA2(accF[2], wf2, xfb.x);
            FMA2(accF[3], wf2, xfb.y);
        }
#pragma unroll
        for (int q = 0; q < 8; q++) {
            ulonglong2 xv = xp[q];
            FMA2(accR[2 * q], wr2, xv.x);
            FMA2(accI[2 * q], wi2, xv.x);
            FMA2(accR[2 * q + 1], wr2, xv.y);
            FMA2(accI[2 * q + 1], wi2, xv.y);
        }
    }

    int lane = t & 31;
    int wid = t >> 5;

    // probabilities for column a = t, all 32 rows
    float prob[RB];
#pragma unroll
    for (int p = 0; p < 16; p++) {
        float r0, r1, i0, i1;
        UNPK(r0, r1, accR[p]);
        UNPK(i0, i1, accI[p]);
        prob[2 * p]     = r0 * r0 + i0 * i0;
        prob[2 * p + 1] = r1 * r1 + i1 * i1;
    }

    float sgn = (lane & 16) ? -1.f : 1.f;
#pragma unroll
    for (int r = 0; r < RB; r++) {
        float a = prob[r], b = sgn * prob[r];
#pragma unroll
        for (int o = 16; o; o >>= 1) {
            a += __shfl_xor_sync(FULL, a, o);
            b += __shfl_xor_sync(FULL, b, o);
        }
        if (lane == 0) { s0s[wid][r] = a; s1s[wid][r] = b; }
    }

    // feature: relu then contract with fW2 (warp covers one fc-half of 64)
    {
        float fb = fb1[fc];
        float fr[8];
#pragma unroll
        for (int p = 0; p < 4; p++) {
            float f0, f1;
            UNPK(f0, f1, accF[p]);
            fr[2 * p]     = fmaxf(f0 + fb, 0.f);
            fr[2 * p + 1] = fmaxf(f1 + fb, 0.f);
        }
#pragma unroll
        for (int i = 0; i < 4; i++) {
            float w2 = fW2[i * 64 + fc];
#pragma unroll
            for (int j = 0; j < 8; j++) {
                float v = fr[j] * w2;
#pragma unroll
                for (int o = 16; o; o >>= 1) v += __shfl_xor_sync(FULL, v, o);
                if (lane == 0) fpart[wid][i][j] = v;
            }
        }
    }
    __syncthreads();

    // z expectations + feature head (128 threads: (r, i))
    if (t < RB * 4) {
        int r = t & (RB - 1), i = t >> 5;
        float S = 0.f, acc = 0.f;
        if (i < 3) {
#pragma unroll
            for (int w = 0; w < 8; w++) {
                float v = s0s[w][r];
                S += v;
                acc += ((w >> (2 - i)) & 1) ? -v : v;
            }
        } else {
#pragma unroll
            for (int w = 0; w < 8; w++) {
                S += s0s[w][r];
                acc += s1s[w][r];
            }
        }
        zs[r][i] = acc / S;
        int wg = 2 * (r >> 3), jj = r & 7;
        cfs[r][i] = tanhf(fpart[wg][i][jj] + fpart[wg + 1][i][jj] + fb2[i]);
    }
    __syncthreads();
    if (t < RB * 4) {
        int r = t & (RB - 1), i = t >> 5;
        hs[r][i] = ab[i] + aW[i * 4 + 0] * zs[r][0] + aW[i * 4 + 1] * zs[r][1]
                         + aW[i * 4 + 2] * zs[r][2] + aW[i * 4 + 3] * zs[r][3]
                 + cfs[r][i];
    }
    __syncthreads();

    // warp 0: write h + 14 h-moment partials (fixed-order trees)
    if (t < 32) {
        float h0 = hs[t][0], h1 = hs[t][1], h2 = hs[t][2], h3 = hs[t][3];
        ((float4*)g_h)[base + t] = make_float4(h0, h1, h2, h3);
        float m[14] = {h0, h1, h2, h3,
                       h0 * h0, h0 * h1, h0 * h2, h0 * h3,
                       h1 * h1, h1 * h2, h1 * h3,
                       h2 * h2, h2 * h3, h3 * h3};
#pragma unroll
        for (int v = 0; v < 14; v++) {
            float s = m[v];
#pragma unroll
            for (int o = 16; o; o >>= 1) s += __shfl_xor_sync(FULL, s, o);
            if (lane == 0) g_part1[blockIdx.x * 16 + v] = s;
        }
    }
}

// ---------------------------------------------------------------------------
// combine1: fp64 reduce 14 h-moments over 256 blocks, then stat1 analytically
// (h1 = cW1 h + cb1 -> mean/var via mean & covariance of h).
// ---------------------------------------------------------------------------
__global__ void __launch_bounds__(512) combine1_kernel(
    const float* __restrict__ cW1, const float* __restrict__ cb1)
{
    __shared__ double mom[14];
    int t = threadIdx.x;
    int grp = t >> 5, lane = t & 31;
    if (grp < 14) {
        double s = 0.0;
#pragma unroll
        for (int i = 0; i < NBLK / 32; i++)
            s += (double)g_part1[(lane + 32 * i) * 16 + grp];
#pragma unroll
        for (int o = 16; o; o >>= 1) s += __shfl_xor_sync(FULL, s, o);
        if (lane == 0) mom[grp] = s;
    }
    __syncthreads();
    if (t < 32) {
        double invB = 1.0 / BATCH;
        double mu[4];
#pragma unroll
        for (int i = 0; i < 4; i++) mu[i] = mom[i] * invB;
        // covariance matrix (biased)
        double C[4][4];
        const int pi[10] = {0, 0, 0, 0, 1, 1, 1, 2, 2, 3};
        const int pj[10] = {0, 1, 2, 3, 1, 2, 3, 2, 3, 3};
#pragma unroll
        for (int p = 0; p < 10; p++) {
            double c = mom[4 + p] * invB - mu[pi[p]] * mu[pj[p]];
            C[pi[p]][pj[p]] = c;
            C[pj[p]][pi[p]] = c;
        }
        double w[4];
#pragma unroll
        for (int i = 0; i < 4; i++) w[i] = (double)cW1[t * 4 + i];
        double mean = (double)cb1[t];
        double var = 0.0;
#pragma unroll
        for (int i = 0; i < 4; i++) {
            mean += w[i] * mu[i];
#pragma unroll
            for (int j = 0; j < 4; j++) var += w[i] * w[j] * C[i][j];
        }
        g_stat1[t] = (float)mean;
        g_stat1[32 + t] = rsqrtf((float)var + 1e-5f);
    }
}

// ---------------------------------------------------------------------------
// bn1: recompute h1 from g_h (16B/row), BN1+relu, cW2 -> g_h2 + BN2 partials.
// 128 blocks x 128 threads; thread = (row, half of 16 outputs).
// ---------------------------------------------------------------------------
__global__ void __launch_bounds__(128) bn1_kernel(
    const float* __restrict__ cW1, const float* __restrict__ cb1,
    const float* __restrict__ g1, const float* __restrict__ be1,
    const float* __restrict__ cW2, const float* __restrict__ cb2)
{
    __shared__ float ovs[64][16];
    int t = threadIdx.x;
    int rl = t >> 1;               // local row 0..63
    int half = t & 1;
    int row = blockIdx.x * 64 + rl;

    float4 h = ((const float4*)g_h)[row];
    float a[32];
#pragma unroll
    for (int j = 0; j < 32; j++) {
        float4 w1 = ((const float4*)cW1)[j];
        float h1 = cb1[j] + w1.x * h.x + w1.y * h.y + w1.z * h.z + w1.w * h.w;
        a[j] = fmaxf(g1[j] * (h1 - g_stat1[j]) * g_stat1[32 + j] + be1[j], 0.f);
    }
    float ov[8];
#pragma unroll
    for (int i = 0; i < 8; i++) {
        int io = half * 8 + i;
        float acc = cb2[io];
#pragma unroll
        for (int j = 0; j < 32; j++) acc = fmaf(cW2[io * 32 + j], a[j], acc);
        ov[i] = acc;
        ovs[rl][io] = acc;
    }
    ((float4*)&g_h2[row * 16 + half * 8])[0] = make_float4(ov[0], ov[1], ov[2], ov[3]);
    ((float4*)&g_h2[row * 16 + half * 8])[1] = make_float4(ov[4], ov[5], ov[6], ov[7]);
    __syncthreads();

    if (t < 32) {
        int f = t & 15, kind = t >> 4;
        float s = 0.f;
        for (int r = 0; r < 64; r++) {
            float v = ovs[r][f];
            s += kind ? v * v : v;
        }
        g_part2[blockIdx.x * 32 + t] = s;
    }
}

__global__ void __launch_bounds__(512) combine2_kernel() {
    int t = threadIdx.x;
    int f = t >> 5, lane = t & 31;         // 16 features x 32 lanes
    double s = 0.0, s2 = 0.0;
#pragma unroll
    for (int i = 0; i < 128 / 32; i++) {
        int b = lane + 32 * i;
        s  += (double)g_part2[b * 32 + f];
        s2 += (double)g_part2[b * 32 + 16 + f];
    }
#pragma unroll
    for (int o = 16; o; o >>= 1) {
        s  += __shfl_xor_sync(FULL, s, o);
        s2 += __shfl_xor_sync(FULL, s2, o);
    }
    if (lane == 0) {
        double mean = s / BATCH;
        double var = s2 / BATCH - mean * mean;
        g_stat2[f] = (float)mean;
        g_stat2[16 + f] = rsqrtf((float)var + 1e-5f);
    }
}

// ---------------------------------------------------------------------------
// final: BN2 + relu + cW3 + relu + cW4 + sigmoid -> out. 64 blocks x 128.
// ---------------------------------------------------------------------------
__global__ void __launch_bounds__(128) final_kernel(
    const float* __restrict__ g2, const float* __restrict__ be2,
    const float* __restrict__ cW3, const float* __restrict__ cb3,
    const float* __restrict__ cW4, const float* __restrict__ cb4,
    float* __restrict__ out)
{
    int r = blockIdx.x * 128 + threadIdx.x;
    float a[16];
    const float4* hp = (const float4*)&g_h2[r * 16];
#pragma unroll
    for (int j4 = 0; j4 < 4; j4++) {
        float4 v = hp[j4];
        float vv[4] = {v.x, v.y, v.z, v.w};
#pragma unroll
        for (int c = 0; c < 4; c++) {
            int j = j4 * 4 + c;
            a[j] = fmaxf(g2[j] * (vv[c] - g_stat2[j]) * g_stat2[16 + j] + be2[j], 0.f);
        }
    }
    float acc4 = cb4[0];
#pragma unroll
    for (int i = 0; i < 8; i++) {
        float acc = cb3[i];
#pragma unroll
        for (int j = 0; j < 16; j++) acc = fmaf(cW3[i * 16 + j], a[j], acc);
        acc = fmaxf(acc, 0.f);
        acc4 = fmaf(cW4[i], acc, acc4);
    }
    out[r] = 1.f / (1.f + expf(-acc4));
}

// ---------------------------------------------------------------------------
extern "C" void kernel_launch(void* const* d_in, const int* in_sizes, int n_in,
                              void* d_out, int out_size) {
    const float* x   = (const float*)d_in[0];
    const float* qw  = (const float*)d_in[1];
    const float* aW  = (const float*)d_in[2];
    const float* ab  = (const float*)d_in[3];
    const float* fW1 = (const float*)d_in[4];
    const float* fb1 = (const float*)d_in[5];
    const float* fW2 = (const float*)d_in[6];
    const float* fb2 = (const float*)d_in[7];
    const float* cW1 = (const float*)d_in[8];
    const float* cb1 = (const float*)d_in[9];
    const float* g1  = (const float*)d_in[10];
    const float* be1 = (const float*)d_in[11];
    const float* cW2 = (const float*)d_in[12];
    const float* cb2 = (const float*)d_in[13];
    const float* g2  = (const float*)d_in[14];
    const float* be2 = (const float*)d_in[15];
    const float* cW3 = (const float*)d_in[16];
    const float* cb3 = (const float*)d_in[17];
    const float* cW4 = (const float*)d_in[18];
    const float* cb4 = (const float*)d_in[19];
    float* out = (float*)d_out;

    prep_kernel<<<33, 256>>>(qw, fW1);
    main_kernel<<<NBLK, 256>>>(x, aW, ab, fb1, fW2, fb2);
    combine1_kernel<<<1, 512>>>(cW1, cb1);
    bn1_kernel<<<128, 128>>>(cW1, cb1, g1, be1, cW2, cb2);
    combine2_kernel<<<1, 512>>>();
    final_kernel<<<64, 128>>>(g2, be2, cW3, cb3, cW4, cb4, out);
}